// round 2
// baseline (speedup 1.0000x reference)
#include <cuda_runtime.h>
#include <cstdint>
#include <cmath>

#define T_SEQ   1024
#define D_MODEL 1024
#define NHEAD   16
#define HDIM    64
#define DFF     4096
#define BATCH   8
#define MROWS   (BATCH * T_SEQ)

// ---------------- scratch (device globals: allocation-free) ----------------
__device__ float g_h1 [(size_t)MROWS * D_MODEL];
__device__ float g_q  [(size_t)MROWS * D_MODEL];
__device__ float g_k  [(size_t)MROWS * D_MODEL];
__device__ float g_v  [(size_t)MROWS * D_MODEL];
__device__ float g_att[(size_t)MROWS * D_MODEL];
__device__ float g_res[(size_t)MROWS * D_MODEL];
__device__ float g_ff [(size_t)MROWS * DFF];

// ---------------- helpers ----------------
__device__ __forceinline__ float warp_sum(float v) {
#pragma unroll
    for (int o = 16; o > 0; o >>= 1) v += __shfl_xor_sync(0xffffffffu, v, o);
    return v;
}
__device__ __forceinline__ float warp_max(float v) {
#pragma unroll
    for (int o = 16; o > 0; o >>= 1) v = fmaxf(v, __shfl_xor_sync(0xffffffffu, v, o));
    return v;
}
__device__ __forceinline__ float tf32_rna(float x) {
    uint32_t u;
    asm("cvt.rna.tf32.f32 %0, %1;" : "=r"(u) : "f"(x));
    return __uint_as_float(u);
}
__device__ __forceinline__ void mma_tf32(float* c, const uint32_t* a, const uint32_t* b) {
    asm volatile(
        "mma.sync.aligned.m16n8k8.row.col.f32.tf32.tf32.f32 "
        "{%0,%1,%2,%3}, {%4,%5,%6,%7}, {%8,%9}, {%0,%1,%2,%3};\n"
        : "+f"(c[0]), "+f"(c[1]), "+f"(c[2]), "+f"(c[3])
        : "r"(a[0]), "r"(a[1]), "r"(a[2]), "r"(a[3]), "r"(b[0]), "r"(b[1]));
}
__device__ __forceinline__ float gelu_tanh(float x) {
    float x3 = x * x * x;
    float u  = 0.7978845608028654f * (x + 0.044715f * x3);
    return 0.5f * x * (1.0f + tanhf(u));
}

// ---------------- LayerNorm (one block per row, D=1024) ----------------
__global__ __launch_bounds__(256) void ln_kernel(
    const float* __restrict__ x, const float* __restrict__ sc,
    const float* __restrict__ bi, float* __restrict__ y)
{
    __shared__ float redm[8], redv[8], bcast[2];
    const int row = blockIdx.x, tid = threadIdx.x;
    const int wid = tid >> 5, lane = tid & 31;

    float4 v = *(const float4*)&x[(size_t)row * D_MODEL + tid * 4];
    float s = v.x + v.y + v.z + v.w;
    s = warp_sum(s);
    if (lane == 0) redm[wid] = s;
    __syncthreads();
    if (tid == 0) {
        float tot = 0.f;
#pragma unroll
        for (int i = 0; i < 8; i++) tot += redm[i];
        bcast[0] = tot * (1.0f / 1024.0f);
    }
    __syncthreads();
    const float mean = bcast[0];
    float dx = v.x - mean, dy = v.y - mean, dz = v.z - mean, dw = v.w - mean;
    float ss = dx * dx + dy * dy + dz * dz + dw * dw;
    ss = warp_sum(ss);
    if (lane == 0) redv[wid] = ss;
    __syncthreads();
    if (tid == 0) {
        float tot = 0.f;
#pragma unroll
        for (int i = 0; i < 8; i++) tot += redv[i];
        bcast[1] = rsqrtf(tot * (1.0f / 1024.0f) + 1e-6f);
    }
    __syncthreads();
    const float rstd = bcast[1];
    float4 scv = *(const float4*)&sc[tid * 4];
    float4 biv = *(const float4*)&bi[tid * 4];
    float4 o;
    o.x = dx * rstd * scv.x + biv.x;
    o.y = dy * rstd * scv.y + biv.y;
    o.z = dz * rstd * scv.z + biv.z;
    o.w = dw * rstd * scv.w + biv.w;
    *(float4*)&y[(size_t)row * D_MODEL + tid * 4] = o;
}

// ---------------- TF32 tensor-core GEMM: C = A[M,K] @ B[K,N] + bias (+res / gelu) ----
// EPI: 0 = bias, 1 = bias + residual, 2 = bias + gelu
template <int EPI>
__global__ __launch_bounds__(256) void gemm_tf32_kernel(
    const float* __restrict__ A, const float* __restrict__ B,
    const float* __restrict__ bias, const float* __restrict__ res,
    float* __restrict__ C, int M, int N, int K)
{
    __shared__ float As[128][36];   // [m][k], pad 36: conflict-free frag loads
    __shared__ float Bs[32][136];   // [k][n], pad 136 (8 mod 32): conflict-free

    const int tid  = threadIdx.x;
    const int wid  = tid >> 5, lane = tid & 31;
    const int g    = lane >> 2, tig = lane & 3;
    const int warpM = (wid >> 2) * 64, warpN = (wid & 3) * 32;
    const int bm = blockIdx.y * 128, bn = blockIdx.x * 128;

    const int arow = tid >> 3;        // 0..31
    const int acol = (tid & 7) * 4;   // 0..28
    const int brow = tid >> 5;        // 0..7
    const int bcol = (tid & 31) * 4;  // 0..124

    const float* Aptr = A + (size_t)(bm + arow) * K + acol;
    const float* Bptr = B + (size_t)brow * N + bn + bcol;

    float4 pa[4], pb[4];
#pragma unroll
    for (int r = 0; r < 4; r++) pa[r] = *(const float4*)(Aptr + (size_t)(32 * r) * K);
#pragma unroll
    for (int r = 0; r < 4; r++) pb[r] = *(const float4*)(Bptr + (size_t)(8 * r) * N);

    float c[4][4][4];
#pragma unroll
    for (int i = 0; i < 4; i++)
#pragma unroll
        for (int j = 0; j < 4; j++)
#pragma unroll
            for (int q = 0; q < 4; q++) c[i][j][q] = 0.f;

    for (int k0 = 0; k0 < K; k0 += 32) {
#pragma unroll
        for (int r = 0; r < 4; r++) {
            float4 t = pa[r];
            float4 s = make_float4(tf32_rna(t.x), tf32_rna(t.y), tf32_rna(t.z), tf32_rna(t.w));
            *(float4*)&As[arow + 32 * r][acol] = s;
        }
#pragma unroll
        for (int r = 0; r < 4; r++) {
            float4 t = pb[r];
            float4 s = make_float4(tf32_rna(t.x), tf32_rna(t.y), tf32_rna(t.z), tf32_rna(t.w));
            *(float4*)&Bs[brow + 8 * r][bcol] = s;
        }
        __syncthreads();

        if (k0 + 32 < K) {
#pragma unroll
            for (int r = 0; r < 4; r++)
                pa[r] = *(const float4*)(Aptr + (size_t)(32 * r) * K + (k0 + 32));
#pragma unroll
            for (int r = 0; r < 4; r++)
                pb[r] = *(const float4*)(Bptr + (size_t)(k0 + 32 + 8 * r) * N);
        }

#pragma unroll
        for (int kk = 0; kk < 32; kk += 8) {
            uint32_t af[4][4], bf[4][2];
#pragma unroll
            for (int i = 0; i < 4; i++) {
                const int r0 = warpM + 16 * i + g;
                af[i][0] = __float_as_uint(As[r0][kk + tig]);
                af[i][1] = __float_as_uint(As[r0 + 8][kk + tig]);
                af[i][2] = __float_as_uint(As[r0][kk + tig + 4]);
                af[i][3] = __float_as_uint(As[r0 + 8][kk + tig + 4]);
            }
#pragma unroll
            for (int j = 0; j < 4; j++) {
                const int cn = warpN + 8 * j + g;
                bf[j][0] = __float_as_uint(Bs[kk + tig][cn]);
                bf[j][1] = __float_as_uint(Bs[kk + tig + 4][cn]);
            }
#pragma unroll
            for (int i = 0; i < 4; i++)
#pragma unroll
                for (int j = 0; j < 4; j++) mma_tf32(c[i][j], af[i], bf[j]);
        }
        __syncthreads();
    }

#pragma unroll
    for (int i = 0; i < 4; i++) {
#pragma unroll
        for (int j = 0; j < 4; j++) {
            const int row0 = bm + warpM + 16 * i + g;
            const int col  = bn + warpN + 8 * j + 2 * tig;
            const float b0 = bias[col], b1 = bias[col + 1];
            float v00 = c[i][j][0] + b0, v01 = c[i][j][1] + b1;
            float v10 = c[i][j][2] + b0, v11 = c[i][j][3] + b1;
            if (EPI == 1) {
                float2 r0 = *(const float2*)&res[(size_t)row0 * N + col];
                float2 r1 = *(const float2*)&res[(size_t)(row0 + 8) * N + col];
                v00 += r0.x; v01 += r0.y; v10 += r1.x; v11 += r1.y;
            }
            if (EPI == 2) {
                v00 = gelu_tanh(v00); v01 = gelu_tanh(v01);
                v10 = gelu_tanh(v10); v11 = gelu_tanh(v11);
            }
            *(float2*)&C[(size_t)row0 * N + col]       = make_float2(v00, v01);
            *(float2*)&C[(size_t)(row0 + 8) * N + col] = make_float2(v10, v11);
        }
    }
}

// ---------------- causal flash attention (fp32), head_dim=64 ----------------
// block = 256 threads handles (b, h, 64 q rows); warp owns 8 q rows.
__global__ __launch_bounds__(256) void attn_kernel(
    const float* __restrict__ Q, const float* __restrict__ K,
    const float* __restrict__ V, float* __restrict__ O)
{
    __shared__ float Qs[64][64];
    __shared__ float Kst[64][33];  // [dim][key] transposed, pad 33
    __shared__ float Vs[32][64];
    __shared__ float4 ps4[8][32];

    const int qt  = (int)gridDim.x - 1 - (int)blockIdx.x;  // big tiles first
    const int bh  = blockIdx.y;
    const int b   = bh >> 4, h = bh & 15;
    const int tid = threadIdx.x, wid = tid >> 5, lane = tid & 31;

    const float* Qg = Q + ((size_t)b * T_SEQ) * D_MODEL + h * HDIM;
    const float* Kg = K + ((size_t)b * T_SEQ) * D_MODEL + h * HDIM;
    const float* Vg = V + ((size_t)b * T_SEQ) * D_MODEL + h * HDIM;

#pragma unroll
    for (int r = 0; r < 4; r++) {
        const int lin = tid + 256 * r;
        const int qr = lin >> 4, c4 = (lin & 15) * 4;
        *(float4*)&Qs[qr][c4] = *(const float4*)&Qg[(size_t)(qt * 64 + qr) * D_MODEL + c4];
    }

    float2 acc[2][4];
    float  mx[2][4], ls[2][4];
#pragma unroll
    for (int gq = 0; gq < 2; gq++)
#pragma unroll
        for (int rr = 0; rr < 4; rr++) {
            acc[gq][rr] = make_float2(0.f, 0.f);
            mx[gq][rr] = -1e30f;
            ls[gq][rr] = 0.f;
        }

    const int nkt = 2 * qt + 2;
    for (int kt = 0; kt < nkt; kt++) {
#pragma unroll
        for (int r = 0; r < 2; r++) {
            const int lin = tid + 256 * r;
            const int key = lin >> 4, c4 = (lin & 15) * 4;
            float4 kv = *(const float4*)&Kg[(size_t)(kt * 32 + key) * D_MODEL + c4];
            Kst[c4 + 0][key] = kv.x;
            Kst[c4 + 1][key] = kv.y;
            Kst[c4 + 2][key] = kv.z;
            Kst[c4 + 3][key] = kv.w;
            *(float4*)&Vs[key][c4] = *(const float4*)&Vg[(size_t)(kt * 32 + key) * D_MODEL + c4];
        }
        __syncthreads();

        const bool mt = (kt >= 2 * qt);
        const int  key = kt * 32 + lane;

#pragma unroll
        for (int gq = 0; gq < 2; gq++) {
            const int r0 = wid * 8 + gq * 4;
            float s[4] = {0.f, 0.f, 0.f, 0.f};
#pragma unroll
            for (int d4 = 0; d4 < 16; d4++) {
                float4 q0 = *(const float4*)&Qs[r0 + 0][d4 * 4];
                float4 q1 = *(const float4*)&Qs[r0 + 1][d4 * 4];
                float4 q2 = *(const float4*)&Qs[r0 + 2][d4 * 4];
                float4 q3 = *(const float4*)&Qs[r0 + 3][d4 * 4];
                float k0 = Kst[4 * d4 + 0][lane], k1 = Kst[4 * d4 + 1][lane];
                float k2 = Kst[4 * d4 + 2][lane], k3 = Kst[4 * d4 + 3][lane];
                s[0] += q0.x * k0 + q0.y * k1 + q0.z * k2 + q0.w * k3;
                s[1] += q1.x * k0 + q1.y * k1 + q1.z * k2 + q1.w * k3;
                s[2] += q2.x * k0 + q2.y * k1 + q2.z * k2 + q2.w * k3;
                s[3] += q3.x * k0 + q3.y * k1 + q3.z * k2 + q3.w * k3;
            }
            float p[4];
#pragma unroll
            for (int rr = 0; rr < 4; rr++) {
                float sv = s[rr] * 0.125f;  // 1/sqrt(64)
                const int qrow = qt * 64 + r0 + rr;
                if (mt && key > qrow) sv = -1e30f;
                float tmax = warp_max(sv);
                float mnew = fmaxf(mx[gq][rr], tmax);
                float pv   = __expf(sv - mnew);
                float corr = __expf(mx[gq][rr] - mnew);
                ls[gq][rr] = ls[gq][rr] * corr + warp_sum(pv);
                acc[gq][rr].x *= corr;
                acc[gq][rr].y *= corr;
                mx[gq][rr] = mnew;
                p[rr] = pv;
            }
            ps4[wid][lane] = make_float4(p[0], p[1], p[2], p[3]);
            __syncwarp();
#pragma unroll 8
            for (int jj = 0; jj < 32; jj++) {
                float4 pj = ps4[wid][jj];
                float2 v  = *(const float2*)&Vs[jj][2 * lane];
                acc[gq][0].x += pj.x * v.x; acc[gq][0].y += pj.x * v.y;
                acc[gq][1].x += pj.y * v.x; acc[gq][1].y += pj.y * v.y;
                acc[gq][2].x += pj.z * v.x; acc[gq][2].y += pj.z * v.y;
                acc[gq][3].x += pj.w * v.x; acc[gq][3].y += pj.w * v.y;
            }
            __syncwarp();
        }
        __syncthreads();
    }

    float* Og = O + ((size_t)b * T_SEQ) * D_MODEL + h * HDIM;
#pragma unroll
    for (int gq = 0; gq < 2; gq++)
#pragma unroll
        for (int rr = 0; rr < 4; rr++) {
            const int row = qt * 64 + wid * 8 + gq * 4 + rr;
            const float inv = 1.0f / ls[gq][rr];
            *(float2*)&Og[(size_t)row * D_MODEL + 2 * lane] =
                make_float2(acc[gq][rr].x * inv, acc[gq][rr].y * inv);
        }
}

// ---------------- launch ----------------
extern "C" void kernel_launch(void* const* d_in, const int* in_sizes, int n_in,
                              void* d_out, int out_size)
{
    const float* x    = (const float*)d_in[0];
    // d_in[1] = mask (causal; implemented analytically)
    const float* ln1s = (const float*)d_in[2];
    const float* ln1b = (const float*)d_in[3];
    const float* wq = (const float*)d_in[4];  const float* bq = (const float*)d_in[5];
    const float* wk = (const float*)d_in[6];  const float* bk = (const float*)d_in[7];
    const float* wv = (const float*)d_in[8];  const float* bv = (const float*)d_in[9];
    const float* wo = (const float*)d_in[10]; const float* bo = (const float*)d_in[11];
    const float* ln2s = (const float*)d_in[12];
    const float* ln2b = (const float*)d_in[13];
    const float* w1 = (const float*)d_in[14]; const float* b1 = (const float*)d_in[15];
    const float* w2 = (const float*)d_in[16]; const float* b2 = (const float*)d_in[17];
    float* out = (float*)d_out;

    float *h1, *q, *k, *v, *att, *res, *ff;
    cudaGetSymbolAddress((void**)&h1,  g_h1);
    cudaGetSymbolAddress((void**)&q,   g_q);
    cudaGetSymbolAddress((void**)&k,   g_k);
    cudaGetSymbolAddress((void**)&v,   g_v);
    cudaGetSymbolAddress((void**)&att, g_att);
    cudaGetSymbolAddress((void**)&res, g_res);
    cudaGetSymbolAddress((void**)&ff,  g_ff);

    const dim3 gD(D_MODEL / 128, MROWS / 128);   // (8, 64)
    const dim3 gF(DFF / 128,     MROWS / 128);   // (32, 64)

    ln_kernel<<<MROWS, 256>>>(x, ln1s, ln1b, h1);
    gemm_tf32_kernel<0><<<gD, 256>>>(h1, wq, bq, nullptr, q, MROWS, D_MODEL, D_MODEL);
    gemm_tf32_kernel<0><<<gD, 256>>>(h1, wk, bk, nullptr, k, MROWS, D_MODEL, D_MODEL);
    gemm_tf32_kernel<0><<<gD, 256>>>(h1, wv, bv, nullptr, v, MROWS, D_MODEL, D_MODEL);
    attn_kernel<<<dim3(T_SEQ / 64, BATCH * NHEAD), 256>>>(q, k, v, att);
    gemm_tf32_kernel<1><<<gD, 256>>>(att, wo, bo, x, res, MROWS, D_MODEL, D_MODEL);
    ln_kernel<<<MROWS, 256>>>(res, ln2s, ln2b, h1);
    gemm_tf32_kernel<2><<<gF, 256>>>(h1, w1, b1, nullptr, ff, MROWS, DFF, D_MODEL);
    gemm_tf32_kernel<1><<<gD, 256>>>(ff, w2, b2, res, out, MROWS, D_MODEL, DFF);
}

// round 4
// speedup vs baseline: 1.5607x; 1.5607x over previous
#include <cuda_runtime.h>
#include <cuda_fp16.h>
#include <cstdint>
#include <cmath>

#define T_SEQ   1024
#define D_MODEL 1024
#define NHEAD   16
#define HDIM    64
#define DFF     4096
#define BATCH   8
#define MROWS   (BATCH * T_SEQ)

// ---------------- scratch (device globals: allocation-free) ----------------
__device__ float  g_h1 [(size_t)MROWS * D_MODEL];
__device__ __half g_q  [(size_t)MROWS * D_MODEL];
__device__ __half g_k  [(size_t)MROWS * D_MODEL];
__device__ __half g_v  [(size_t)MROWS * D_MODEL];
__device__ float  g_att[(size_t)MROWS * D_MODEL];
__device__ float  g_res[(size_t)MROWS * D_MODEL];
__device__ float  g_ff [(size_t)MROWS * DFF];
__device__ float  g_wqT[(size_t)D_MODEL * D_MODEL];
__device__ float  g_wkT[(size_t)D_MODEL * D_MODEL];
__device__ float  g_wvT[(size_t)D_MODEL * D_MODEL];
__device__ float  g_woT[(size_t)D_MODEL * D_MODEL];
__device__ float  g_w1T[(size_t)D_MODEL * DFF];
__device__ float  g_w2T[(size_t)D_MODEL * DFF];

// ---------------- helpers ----------------
__device__ __forceinline__ uint32_t smem_u32(const void* p) {
    uint32_t a;
    asm("{ .reg .u64 t; cvta.to.shared.u64 t, %1; cvt.u32.u64 %0, t; }" : "=r"(a) : "l"(p));
    return a;
}
__device__ __forceinline__ float warp_sum(float v) {
#pragma unroll
    for (int o = 16; o > 0; o >>= 1) v += __shfl_xor_sync(0xffffffffu, v, o);
    return v;
}
__device__ __forceinline__ float tf32_rna(float x) {
    uint32_t u;
    asm("cvt.rna.tf32.f32 %0, %1;" : "=r"(u) : "f"(x));
    return __uint_as_float(u);
}
__device__ __forceinline__ float fast_ex2(float x) {
    float y;
    asm("ex2.approx.f32 %0, %1;" : "=f"(y) : "f"(x));
    return y;
}
__device__ __forceinline__ float fast_tanh(float x) {
    float y;
    asm("tanh.approx.f32 %0, %1;" : "=f"(y) : "f"(x));
    return y;
}
__device__ __forceinline__ float gelu_tanh(float x) {
    float x3 = x * x * x;
    float u  = 0.7978845608028654f * (x + 0.044715f * x3);
    return 0.5f * x * (1.0f + fast_tanh(u));
}
__device__ __forceinline__ void mma_tf32(float* c, const uint32_t* a, uint32_t b0, uint32_t b1) {
    asm volatile(
        "mma.sync.aligned.m16n8k8.row.col.f32.tf32.tf32.f32 "
        "{%0,%1,%2,%3}, {%4,%5,%6,%7}, {%8,%9}, {%0,%1,%2,%3};\n"
        : "+f"(c[0]), "+f"(c[1]), "+f"(c[2]), "+f"(c[3])
        : "r"(a[0]), "r"(a[1]), "r"(a[2]), "r"(a[3]), "r"(b0), "r"(b1));
}
__device__ __forceinline__ void mma_f16(float* c, const uint32_t* a, uint32_t b0, uint32_t b1) {
    asm volatile(
        "mma.sync.aligned.m16n8k16.row.col.f32.f16.f16.f32 "
        "{%0,%1,%2,%3}, {%4,%5,%6,%7}, {%8,%9}, {%0,%1,%2,%3};\n"
        : "+f"(c[0]), "+f"(c[1]), "+f"(c[2]), "+f"(c[3])
        : "r"(a[0]), "r"(a[1]), "r"(a[2]), "r"(a[3]), "r"(b0), "r"(b1));
}
__device__ __forceinline__ void ldsm4(uint32_t* r, uint32_t addr) {
    asm volatile("ldmatrix.sync.aligned.m8n8.x4.shared.b16 {%0,%1,%2,%3}, [%4];"
        : "=r"(r[0]), "=r"(r[1]), "=r"(r[2]), "=r"(r[3]) : "r"(addr));
}
__device__ __forceinline__ uint32_t f22h2(float lo, float hi) {
    uint32_t u;
    asm("cvt.rn.f16x2.f32 %0, %1, %2;" : "=r"(u) : "f"(hi), "f"(lo));
    return u;
}
__device__ __forceinline__ void cp16(uint32_t dst, const void* src) {
    asm volatile("cp.async.cg.shared.global [%0], [%1], 16;" :: "r"(dst), "l"(src));
}
#define CP_COMMIT() asm volatile("cp.async.commit_group;" ::: "memory")
#define CP_WAIT1()  asm volatile("cp.async.wait_group 1;" ::: "memory")
#define CP_WAIT0()  asm volatile("cp.async.wait_group 0;" ::: "memory")

// ---------------- weight transpose + tf32 round: out[C][R] = rna(in[R][C]) ----
__global__ __launch_bounds__(256) void transpose_rna_kernel(
    const float* __restrict__ in, float* __restrict__ out, int R, int C)
{
    __shared__ float t[32][33];
    const int bx = blockIdx.x * 32, by = blockIdx.y * 32;
    const int tx = threadIdx.x, ty = threadIdx.y;  // (32, 8)
#pragma unroll
    for (int i = 0; i < 4; i++)
        t[ty + 8 * i][tx] = in[(size_t)(by + ty + 8 * i) * C + bx + tx];
    __syncthreads();
#pragma unroll
    for (int i = 0; i < 4; i++)
        out[(size_t)(bx + ty + 8 * i) * R + by + tx] = tf32_rna(t[tx][ty + 8 * i]);
}

// ---------------- LayerNorm (output tf32-rounded: feeds GEMM A operands) ----
__global__ __launch_bounds__(256) void ln_kernel(
    const float* __restrict__ x, const float* __restrict__ sc,
    const float* __restrict__ bi, float* __restrict__ y)
{
    __shared__ float redm[8], redv[8], bcast[2];
    const int row = blockIdx.x, tid = threadIdx.x;
    const int wid = tid >> 5, lane = tid & 31;

    float4 v = *(const float4*)&x[(size_t)row * D_MODEL + tid * 4];
    float s = warp_sum(v.x + v.y + v.z + v.w);
    if (lane == 0) redm[wid] = s;
    __syncthreads();
    if (tid == 0) {
        float tot = 0.f;
#pragma unroll
        for (int i = 0; i < 8; i++) tot += redm[i];
        bcast[0] = tot * (1.0f / 1024.0f);
    }
    __syncthreads();
    const float mean = bcast[0];
    float dx = v.x - mean, dy = v.y - mean, dz = v.z - mean, dw = v.w - mean;
    float ss = warp_sum(dx * dx + dy * dy + dz * dz + dw * dw);
    if (lane == 0) redv[wid] = ss;
    __syncthreads();
    if (tid == 0) {
        float tot = 0.f;
#pragma unroll
        for (int i = 0; i < 8; i++) tot += redv[i];
        bcast[1] = rsqrtf(tot * (1.0f / 1024.0f) + 1e-6f);
    }
    __syncthreads();
    const float rstd = bcast[1];
    float4 scv = *(const float4*)&sc[tid * 4];
    float4 biv = *(const float4*)&bi[tid * 4];
    float4 o;
    o.x = tf32_rna(dx * rstd * scv.x + biv.x);
    o.y = tf32_rna(dy * rstd * scv.y + biv.y);
    o.z = tf32_rna(dz * rstd * scv.z + biv.z);
    o.w = tf32_rna(dw * rstd * scv.w + biv.w);
    *(float4*)&y[(size_t)row * D_MODEL + tid * 4] = o;
}

// ---------------- TF32 GEMM, cp.async double-buffered ----------------
// C = A[M,K] @ Bt[N,K]^T + bias; EPI: 1 = +res (f32), 2 = gelu+rna (f32), 3 = half out
// A and Bt must be pre-rounded to tf32. CTA 128x128, k-chunk 32, 2 stages.
#define GSTG 4608  // floats per operand stage (128 rows * 36)

template <int EPI>
__global__ __launch_bounds__(256, 2) void gemm_cp_kernel(
    const float* __restrict__ A, const float* __restrict__ Bt,
    const float* __restrict__ bias, const float* __restrict__ res,
    void* __restrict__ Cv, int M, int N, int K)
{
    extern __shared__ float sm[];
    const uint32_t smb = smem_u32(sm);
    const int tid = threadIdx.x;
    const int wid = tid >> 5, lane = tid & 31;
    const int g = lane >> 2, t = lane & 3;
    const int warpM = (wid >> 2) * 64, warpN = (wid & 3) * 32;
    const int bm = blockIdx.y * 128, bn = blockIdx.x * 128;
    const int nch = K >> 5;

    const float* Ab = A + (size_t)bm * K;
    const float* Bb = Bt + (size_t)bn * K;
    const int crow = tid >> 3, ccol = (tid & 7) * 4;

    // preload chunk 0 into stage 0
    {
        const uint32_t da = smb + (uint32_t)(crow * 36 + ccol) * 4;
        const uint32_t db = smb + (uint32_t)(2 * GSTG + crow * 36 + ccol) * 4;
        const float* sa = Ab + (size_t)crow * K + ccol;
        const float* sb = Bb + (size_t)crow * K + ccol;
#pragma unroll
        for (int r = 0; r < 4; r++) {
            cp16(da + r * 4608u, sa + (size_t)(32 * r) * K);
            cp16(db + r * 4608u, sb + (size_t)(32 * r) * K);
        }
        CP_COMMIT();
    }

    float c[4][4][4];
#pragma unroll
    for (int i = 0; i < 4; i++)
#pragma unroll
        for (int j = 0; j < 4; j++)
#pragma unroll
            for (int q = 0; q < 4; q++) c[i][j][q] = 0.f;

    for (int ch = 0; ch < nch; ch++) {
        const int s = ch & 1;
        if (ch + 1 < nch) {
            const int k0 = (ch + 1) << 5;
            const uint32_t da = smb + (uint32_t)((s ^ 1) * GSTG + crow * 36 + ccol) * 4;
            const uint32_t db = smb + (uint32_t)((2 + (s ^ 1)) * GSTG + crow * 36 + ccol) * 4;
            const float* sa = Ab + (size_t)crow * K + k0 + ccol;
            const float* sb = Bb + (size_t)crow * K + k0 + ccol;
#pragma unroll
            for (int r = 0; r < 4; r++) {
                cp16(da + r * 4608u, sa + (size_t)(32 * r) * K);
                cp16(db + r * 4608u, sb + (size_t)(32 * r) * K);
            }
            CP_COMMIT();
            CP_WAIT1();
        } else {
            CP_WAIT0();
        }
        __syncthreads();

        const float* As_ = sm + s * GSTG;
        const float* Bs_ = sm + (2 + s) * GSTG;
#pragma unroll
        for (int kk = 0; kk < 32; kk += 8) {
            uint32_t af[4][4], bf[4][2];
#pragma unroll
            for (int i = 0; i < 4; i++) {
                const int r0 = warpM + 16 * i + g;
                af[i][0] = __float_as_uint(As_[r0 * 36 + kk + t]);
                af[i][1] = __float_as_uint(As_[(r0 + 8) * 36 + kk + t]);
                af[i][2] = __float_as_uint(As_[r0 * 36 + kk + t + 4]);
                af[i][3] = __float_as_uint(As_[(r0 + 8) * 36 + kk + t + 4]);
            }
#pragma unroll
            for (int j = 0; j < 4; j++) {
                const int n0 = warpN + 8 * j + g;
                bf[j][0] = __float_as_uint(Bs_[n0 * 36 + kk + t]);
                bf[j][1] = __float_as_uint(Bs_[n0 * 36 + kk + t + 4]);
            }
#pragma unroll
            for (int i = 0; i < 4; i++)
#pragma unroll
                for (int j = 0; j < 4; j++) mma_tf32(c[i][j], af[i], bf[j][0], bf[j][1]);
        }
        __syncthreads();
    }

    // epilogue
#pragma unroll
    for (int i = 0; i < 4; i++) {
#pragma unroll
        for (int j = 0; j < 4; j++) {
            const int row0 = bm + warpM + 16 * i + g;
            const int col  = bn + warpN + 8 * j + 2 * t;
            const float b0 = bias[col], b1 = bias[col + 1];
            float v00 = c[i][j][0] + b0, v01 = c[i][j][1] + b1;
            float v10 = c[i][j][2] + b0, v11 = c[i][j][3] + b1;
            if (EPI == 1) {
                float* C = (float*)Cv;
                float2 r0 = *(const float2*)&res[(size_t)row0 * N + col];
                float2 r1 = *(const float2*)&res[(size_t)(row0 + 8) * N + col];
                *(float2*)&C[(size_t)row0 * N + col]       = make_float2(v00 + r0.x, v01 + r0.y);
                *(float2*)&C[(size_t)(row0 + 8) * N + col] = make_float2(v10 + r1.x, v11 + r1.y);
            } else if (EPI == 2) {
                float* C = (float*)Cv;
                *(float2*)&C[(size_t)row0 * N + col] =
                    make_float2(tf32_rna(gelu_tanh(v00)), tf32_rna(gelu_tanh(v01)));
                *(float2*)&C[(size_t)(row0 + 8) * N + col] =
                    make_float2(tf32_rna(gelu_tanh(v10)), tf32_rna(gelu_tanh(v11)));
            } else {  // EPI == 3: half output
                __half* C = (__half*)Cv;
                *(__half2*)&C[(size_t)row0 * N + col]       = __floats2half2_rn(v00, v01);
                *(__half2*)&C[(size_t)(row0 + 8) * N + col] = __floats2half2_rn(v10, v11);
            }
        }
    }
}

// ---------------- tensor-core causal flash attention (fp16 mma, fp32 accum) ----
// block: 256 threads, 128 q-rows; kv tiles of 64; warp owns 16 q-rows.
__global__ __launch_bounds__(256, 2) void attn_tc_kernel(
    const __half* __restrict__ Qh, const __half* __restrict__ Kh,
    const __half* __restrict__ Vh, float* __restrict__ O)
{
    __shared__ uint32_t Qs[128][36];  // half2 pairs along head-dim
    __shared__ uint32_t Ks[64][36];
    __shared__ uint32_t Vt[64][36];   // [dim][key-pair]

    const int qt  = (int)gridDim.x - 1 - (int)blockIdx.x;  // big tiles first
    const int bh  = blockIdx.y;
    const int b   = bh >> 4, h = bh & 15;
    const int tid = threadIdx.x, wid = tid >> 5, lane = tid & 31;
    const int g = lane >> 2, t = lane & 3;
    const int qb = qt * 128;
    const size_t bb = (size_t)b * T_SEQ;
    const int hb = h * HDIM;
    const int r0 = wid * 16;

    // load Q tile (128 rows x 64 halves)
#pragma unroll
    for (int r = 0; r < 4; r++) {
        const int lin = tid + 256 * r;
        const int row = lin >> 3, c = lin & 7;
        *(uint4*)&Qs[row][4 * c] =
            *(const uint4*)&Qh[(bb + qb + row) * D_MODEL + hb + 8 * c];
    }
    __syncthreads();

    // hoisted Q a-fragments: qa[km][0..3]
    uint32_t qa[4][4];
    {
        const uint32_t qbase = smem_u32(Qs);
        const int mi = lane >> 3, mr = lane & 7;
        const int rowoff = (mi & 1) * 8, koff = (mi >> 1) * 4;
#pragma unroll
        for (int km = 0; km < 4; km++)
            ldsm4(qa[km], qbase + (uint32_t)((r0 + rowoff + mr) * 36 + km * 8 + koff) * 4);
    }

    float o[8][4];
#pragma unroll
    for (int j = 0; j < 8; j++)
#pragma unroll
        for (int q = 0; q < 4; q++) o[j][q] = 0.f;
    float m_g = -1e30f, m_g8 = -1e30f, l_g = 0.f, l_g8 = 0.f;
    const float SC = 0.18033688011112042f;  // (1/8) * log2(e)

    const uint32_t kbase = smem_u32(Ks), vbase = smem_u32(Vt);
    const int mi = lane >> 3, mr = lane & 7;

    const int nkt = 2 * qt + 2;
    for (int kt = 0; kt < nkt; kt++) {
        const int k0 = kt * 64;
        // load K tile [64 keys][64 dims]
#pragma unroll
        for (int r = 0; r < 2; r++) {
            const int lin = tid + 256 * r;
            const int row = lin >> 3, c = lin & 7;
            *(uint4*)&Ks[row][4 * c] =
                *(const uint4*)&Kh[(bb + k0 + row) * D_MODEL + hb + 8 * c];
        }
        // load V transposed: Vt[dim][keypair]
        {
            const int kp = tid & 31, d8 = (tid >> 5) * 8;
            const __half* v0p = &Vh[(bb + k0 + 2 * kp) * D_MODEL + hb + d8];
            uint4 v0 = *(const uint4*)v0p;
            uint4 v1 = *(const uint4*)(v0p + D_MODEL);
            const ushort* a0 = (const ushort*)&v0;
            const ushort* a1 = (const ushort*)&v1;
#pragma unroll
            for (int i = 0; i < 8; i++)
                Vt[d8 + i][kp] = (uint32_t)a0[i] | ((uint32_t)a1[i] << 16);
        }
        __syncthreads();

        // S = Q K^T
        float s[8][4];
#pragma unroll
        for (int j = 0; j < 8; j++) {
            uint32_t kb[8];
            const uint32_t ab = kbase + (uint32_t)((8 * j + mr) * 36 + mi * 4) * 4;
            ldsm4(kb, ab);
            ldsm4(kb + 4, ab + 64);
            s[j][0] = s[j][1] = s[j][2] = s[j][3] = 0.f;
            mma_f16(s[j], qa[0], kb[0], kb[1]);
            mma_f16(s[j], qa[1], kb[2], kb[3]);
            mma_f16(s[j], qa[2], kb[4], kb[5]);
            mma_f16(s[j], qa[3], kb[6], kb[7]);
        }

        // causal mask (last two tiles only)
        if (kt >= 2 * qt) {
            const int rg = qb + r0 + g;
#pragma unroll
            for (int j = 0; j < 8; j++) {
                const int col = k0 + 8 * j + 2 * t;
                if (col     > rg)     s[j][0] = -1e30f;
                if (col + 1 > rg)     s[j][1] = -1e30f;
                if (col     > rg + 8) s[j][2] = -1e30f;
                if (col + 1 > rg + 8) s[j][3] = -1e30f;
            }
        }

        // online softmax (base-2)
        float mg = -1e30f, mg8 = -1e30f;
#pragma unroll
        for (int j = 0; j < 8; j++) {
            mg  = fmaxf(mg,  fmaxf(s[j][0], s[j][1]));
            mg8 = fmaxf(mg8, fmaxf(s[j][2], s[j][3]));
        }
        mg  = fmaxf(mg,  __shfl_xor_sync(0xffffffffu, mg, 1));
        mg  = fmaxf(mg,  __shfl_xor_sync(0xffffffffu, mg, 2));
        mg8 = fmaxf(mg8, __shfl_xor_sync(0xffffffffu, mg8, 1));
        mg8 = fmaxf(mg8, __shfl_xor_sync(0xffffffffu, mg8, 2));
        const float mng  = fmaxf(m_g, mg);
        const float mng8 = fmaxf(m_g8, mg8);
        const float corr  = fast_ex2((m_g  - mng)  * SC);
        const float corr8 = fast_ex2((m_g8 - mng8) * SC);
        float sg = 0.f, sg8 = 0.f;
#pragma unroll
        for (int j = 0; j < 8; j++) {
            s[j][0] = fast_ex2((s[j][0] - mng)  * SC);
            s[j][1] = fast_ex2((s[j][1] - mng)  * SC);
            s[j][2] = fast_ex2((s[j][2] - mng8) * SC);
            s[j][3] = fast_ex2((s[j][3] - mng8) * SC);
            sg  += s[j][0] + s[j][1];
            sg8 += s[j][2] + s[j][3];
        }
        sg  += __shfl_xor_sync(0xffffffffu, sg, 1);
        sg  += __shfl_xor_sync(0xffffffffu, sg, 2);
        sg8 += __shfl_xor_sync(0xffffffffu, sg8, 1);
        sg8 += __shfl_xor_sync(0xffffffffu, sg8, 2);
        l_g  = l_g  * corr  + sg;
        l_g8 = l_g8 * corr8 + sg8;
        m_g = mng; m_g8 = mng8;
#pragma unroll
        for (int j = 0; j < 8; j++) {
            o[j][0] *= corr;  o[j][1] *= corr;
            o[j][2] *= corr8; o[j][3] *= corr8;
        }

        // P fragments (register-only c-frag -> a-frag conversion)
        uint32_t pa[4][4];
#pragma unroll
        for (int km = 0; km < 4; km++) {
            pa[km][0] = f22h2(s[2 * km][0], s[2 * km][1]);
            pa[km][1] = f22h2(s[2 * km][2], s[2 * km][3]);
            pa[km][2] = f22h2(s[2 * km + 1][0], s[2 * km + 1][1]);
            pa[km][3] = f22h2(s[2 * km + 1][2], s[2 * km + 1][3]);
        }

        // O += P V
#pragma unroll
        for (int j = 0; j < 8; j++) {
            uint32_t vb[8];
            const uint32_t ab = vbase + (uint32_t)((8 * j + mr) * 36 + mi * 4) * 4;
            ldsm4(vb, ab);
            ldsm4(vb + 4, ab + 64);
            mma_f16(o[j], pa[0], vb[0], vb[1]);
            mma_f16(o[j], pa[1], vb[2], vb[3]);
            mma_f16(o[j], pa[2], vb[4], vb[5]);
            mma_f16(o[j], pa[3], vb[6], vb[7]);
        }
        __syncthreads();
    }

    const float ig = 1.0f / l_g, ig8 = 1.0f / l_g8;
    float* Og = O + (bb + qb + r0) * D_MODEL + hb;
#pragma unroll
    for (int j = 0; j < 8; j++) {
        const int col = 8 * j + 2 * t;
        *(float2*)&Og[(size_t)g * D_MODEL + col] =
            make_float2(tf32_rna(o[j][0] * ig), tf32_rna(o[j][1] * ig));
        *(float2*)&Og[(size_t)(g + 8) * D_MODEL + col] =
            make_float2(tf32_rna(o[j][2] * ig8), tf32_rna(o[j][3] * ig8));
    }
}

// ---------------- launch ----------------
#define GEMM_SMEM (4 * GSTG * 4)  // 73728 bytes

extern "C" void kernel_launch(void* const* d_in, const int* in_sizes, int n_in,
                              void* d_out, int out_size)
{
    const float* x    = (const float*)d_in[0];
    const float* ln1s = (const float*)d_in[2];
    const float* ln1b = (const float*)d_in[3];
    const float* wq = (const float*)d_in[4];  const float* bq = (const float*)d_in[5];
    const float* wk = (const float*)d_in[6];  const float* bk = (const float*)d_in[7];
    const float* wv = (const float*)d_in[8];  const float* bv = (const float*)d_in[9];
    const float* wo = (const float*)d_in[10]; const float* bo = (const float*)d_in[11];
    const float* ln2s = (const float*)d_in[12];
    const float* ln2b = (const float*)d_in[13];
    const float* w1 = (const float*)d_in[14]; const float* b1 = (const float*)d_in[15];
    const float* w2 = (const float*)d_in[16]; const float* b2 = (const float*)d_in[17];
    float* out = (float*)d_out;

    float *h1, *att, *res, *ff;
    __half *q, *k, *v;
    float *wqT, *wkT, *wvT, *woT, *w1T, *w2T;
    cudaGetSymbolAddress((void**)&h1,  g_h1);
    cudaGetSymbolAddress((void**)&q,   g_q);
    cudaGetSymbolAddress((void**)&k,   g_k);
    cudaGetSymbolAddress((void**)&v,   g_v);
    cudaGetSymbolAddress((void**)&att, g_att);
    cudaGetSymbolAddress((void**)&res, g_res);
    cudaGetSymbolAddress((void**)&ff,  g_ff);
    cudaGetSymbolAddress((void**)&wqT, g_wqT);
    cudaGetSymbolAddress((void**)&wkT, g_wkT);
    cudaGetSymbolAddress((void**)&wvT, g_wvT);
    cudaGetSymbolAddress((void**)&woT, g_woT);
    cudaGetSymbolAddress((void**)&w1T, g_w1T);
    cudaGetSymbolAddress((void**)&w2T, g_w2T);

    cudaFuncSetAttribute(gemm_cp_kernel<1>, cudaFuncAttributeMaxDynamicSharedMemorySize, GEMM_SMEM);
    cudaFuncSetAttribute(gemm_cp_kernel<2>, cudaFuncAttributeMaxDynamicSharedMemorySize, GEMM_SMEM);
    cudaFuncSetAttribute(gemm_cp_kernel<3>, cudaFuncAttributeMaxDynamicSharedMemorySize, GEMM_SMEM);

    const dim3 tb(32, 8);
    transpose_rna_kernel<<<dim3(D_MODEL / 32, D_MODEL / 32), tb>>>(wq, wqT, D_MODEL, D_MODEL);
    transpose_rna_kernel<<<dim3(D_MODEL / 32, D_MODEL / 32), tb>>>(wk, wkT, D_MODEL, D_MODEL);
    transpose_rna_kernel<<<dim3(D_MODEL / 32, D_MODEL / 32), tb>>>(wv, wvT, D_MODEL, D_MODEL);
    transpose_rna_kernel<<<dim3(D_MODEL / 32, D_MODEL / 32), tb>>>(wo, woT, D_MODEL, D_MODEL);
    transpose_rna_kernel<<<dim3(DFF / 32, D_MODEL / 32), tb>>>(w1, w1T, D_MODEL, DFF);
    transpose_rna_kernel<<<dim3(D_MODEL / 32, DFF / 32), tb>>>(w2, w2T, DFF, D_MODEL);

    const dim3 gD(D_MODEL / 128, MROWS / 128);   // (8, 64)
    const dim3 gF(DFF / 128,     MROWS / 128);   // (32, 64)

    ln_kernel<<<MROWS, 256>>>(x, ln1s, ln1b, h1);
    gemm_cp_kernel<3><<<gD, 256, GEMM_SMEM>>>(h1, wqT, bq, nullptr, q, MROWS, D_MODEL, D_MODEL);
    gemm_cp_kernel<3><<<gD, 256, GEMM_SMEM>>>(h1, wkT, bk, nullptr, k, MROWS, D_MODEL, D_MODEL);
    gemm_cp_kernel<3><<<gD, 256, GEMM_SMEM>>>(h1, wvT, bv, nullptr, v, MROWS, D_MODEL, D_MODEL);
    attn_tc_kernel<<<dim3(T_SEQ / 128, BATCH * NHEAD), 256>>>(q, k, v, att);
    gemm_cp_kernel<1><<<gD, 256, GEMM_SMEM>>>(att, woT, bo, x, res, MROWS, D_MODEL, D_MODEL);
    ln_kernel<<<MROWS, 256>>>(res, ln2s, ln2b, h1);
    gemm_cp_kernel<2><<<gF, 256, GEMM_SMEM>>>(h1, w1T, b1, nullptr, ff, MROWS, DFF, D_MODEL);
    gemm_cp_kernel<1><<<gD, 256, GEMM_SMEM>>>(ff, w2T, b2, res, out, MROWS, D_MODEL, DFF);
}

// round 5
// speedup vs baseline: 2.9055x; 1.8617x over previous
#include <cuda_runtime.h>
#include <cuda_fp16.h>
#include <cstdint>
#include <cmath>

#define T_SEQ   1024
#define D_MODEL 1024
#define NHEAD   16
#define HDIM    64
#define DFF     4096
#define BATCH   8
#define MROWS   (BATCH * T_SEQ)
#define QKV_N   (3 * D_MODEL)

// ---------------- scratch (device globals: allocation-free) ----------------
__device__ __half g_h1 [(size_t)MROWS * D_MODEL];
__device__ __half g_qkv[(size_t)MROWS * QKV_N];
__device__ __half g_att[(size_t)MROWS * D_MODEL];
__device__ float  g_res[(size_t)MROWS * D_MODEL];
__device__ __half g_ff [(size_t)MROWS * DFF];
__device__ __half g_wqkvT[(size_t)QKV_N * D_MODEL];
__device__ __half g_woT[(size_t)D_MODEL * D_MODEL];
__device__ __half g_w1T[(size_t)DFF * D_MODEL];
__device__ __half g_w2T[(size_t)D_MODEL * DFF];
__device__ float  g_bqkv[QKV_N];

// ---------------- helpers ----------------
__device__ __forceinline__ uint32_t smem_u32(const void* p) {
    uint32_t a;
    asm("{ .reg .u64 t; cvta.to.shared.u64 t, %1; cvt.u32.u64 %0, t; }" : "=r"(a) : "l"(p));
    return a;
}
__device__ __forceinline__ float warp_sum(float v) {
#pragma unroll
    for (int o = 16; o > 0; o >>= 1) v += __shfl_xor_sync(0xffffffffu, v, o);
    return v;
}
__device__ __forceinline__ float fast_ex2(float x) {
    float y; asm("ex2.approx.f32 %0, %1;" : "=f"(y) : "f"(x)); return y;
}
__device__ __forceinline__ float fast_tanh(float x) {
    float y; asm("tanh.approx.f32 %0, %1;" : "=f"(y) : "f"(x)); return y;
}
__device__ __forceinline__ float gelu_tanh(float x) {
    float x3 = x * x * x;
    float u  = 0.7978845608028654f * (x + 0.044715f * x3);
    return 0.5f * x * (1.0f + fast_tanh(u));
}
__device__ __forceinline__ void mma_f16(float* c, const uint32_t* a, uint32_t b0, uint32_t b1) {
    asm volatile(
        "mma.sync.aligned.m16n8k16.row.col.f32.f16.f16.f32 "
        "{%0,%1,%2,%3}, {%4,%5,%6,%7}, {%8,%9}, {%0,%1,%2,%3};\n"
        : "+f"(c[0]), "+f"(c[1]), "+f"(c[2]), "+f"(c[3])
        : "r"(a[0]), "r"(a[1]), "r"(a[2]), "r"(a[3]), "r"(b0), "r"(b1));
}
__device__ __forceinline__ void ldsm4(uint32_t* r, uint32_t addr) {
    asm volatile("ldmatrix.sync.aligned.m8n8.x4.shared.b16 {%0,%1,%2,%3}, [%4];"
        : "=r"(r[0]), "=r"(r[1]), "=r"(r[2]), "=r"(r[3]) : "r"(addr));
}
__device__ __forceinline__ uint32_t f22h2(float lo, float hi) {
    uint32_t u;
    asm("cvt.rn.f16x2.f32 %0, %1, %2;" : "=r"(u) : "f"(hi), "f"(lo));
    return u;
}
__device__ __forceinline__ void cp16(uint32_t dst, const void* src) {
    asm volatile("cp.async.cg.shared.global [%0], [%1], 16;" :: "r"(dst), "l"(src));
}
#define CP_COMMIT() asm volatile("cp.async.commit_group;" ::: "memory")
#define CP_WAIT1()  asm volatile("cp.async.wait_group 1;" ::: "memory")
#define CP_WAIT0()  asm volatile("cp.async.wait_group 0;" ::: "memory")

// ---------------- weight transpose -> half: out[C][R] = (half)in[R][C] ----
__global__ __launch_bounds__(256) void transpose_h_kernel(
    const float* __restrict__ in, __half* __restrict__ out, int R, int C)
{
    __shared__ float t[32][33];
    const int bx = blockIdx.x * 32, by = blockIdx.y * 32;
    const int tx = threadIdx.x, ty = threadIdx.y;  // (32, 8)
#pragma unroll
    for (int i = 0; i < 4; i++)
        t[ty + 8 * i][tx] = in[(size_t)(by + ty + 8 * i) * C + bx + tx];
    __syncthreads();
#pragma unroll
    for (int i = 0; i < 4; i++)
        out[(size_t)(bx + ty + 8 * i) * R + by + tx] = __float2half_rn(t[tx][ty + 8 * i]);
}

__global__ void bias_concat_kernel(const float* __restrict__ bq,
                                   const float* __restrict__ bk,
                                   const float* __restrict__ bv,
                                   float* __restrict__ o)
{
    const int i = blockIdx.x * 256 + threadIdx.x;
    o[i] = (i < D_MODEL) ? bq[i] : (i < 2 * D_MODEL) ? bk[i - D_MODEL] : bv[i - 2 * D_MODEL];
}

// ---------------- LayerNorm (f32 in -> half out) ----------------
__global__ __launch_bounds__(256) void ln_kernel(
    const float* __restrict__ x, const float* __restrict__ sc,
    const float* __restrict__ bi, __half* __restrict__ y)
{
    __shared__ float redm[8], redv[8], bcast[2];
    const int row = blockIdx.x, tid = threadIdx.x;
    const int wid = tid >> 5, lane = tid & 31;

    float4 v = *(const float4*)&x[(size_t)row * D_MODEL + tid * 4];
    float s = warp_sum(v.x + v.y + v.z + v.w);
    if (lane == 0) redm[wid] = s;
    __syncthreads();
    if (tid == 0) {
        float tot = 0.f;
#pragma unroll
        for (int i = 0; i < 8; i++) tot += redm[i];
        bcast[0] = tot * (1.0f / 1024.0f);
    }
    __syncthreads();
    const float mean = bcast[0];
    float dx = v.x - mean, dy = v.y - mean, dz = v.z - mean, dw = v.w - mean;
    float ss = warp_sum(dx * dx + dy * dy + dz * dz + dw * dw);
    if (lane == 0) redv[wid] = ss;
    __syncthreads();
    if (tid == 0) {
        float tot = 0.f;
#pragma unroll
        for (int i = 0; i < 8; i++) tot += redv[i];
        bcast[1] = rsqrtf(tot * (1.0f / 1024.0f) + 1e-6f);
    }
    __syncthreads();
    const float rstd = bcast[1];
    float4 scv = *(const float4*)&sc[tid * 4];
    float4 biv = *(const float4*)&bi[tid * 4];
    __half2* yp = (__half2*)&y[(size_t)row * D_MODEL + tid * 4];
    yp[0] = __floats2half2_rn(dx * rstd * scv.x + biv.x, dy * rstd * scv.y + biv.y);
    yp[1] = __floats2half2_rn(dz * rstd * scv.z + biv.z, dw * rstd * scv.w + biv.w);
}

// ---------------- fp16 GEMM, cp.async double-buffered ----------------
// C = A[M,K] @ Bt[N,K]^T + bias; EPI: 1 = f32 +res, 2 = half gelu, 3 = half
// CTA 128x128, k-chunk 64 halves (128B rows), 2 stages.
// SMEM stage: uint32[128][36] per operand (pitch 72 halves).
#define HSTG 4608  // uint32 per operand stage
#define GEMM_SMEM (4 * HSTG * 4)  // 73728 bytes

template <int EPI>
__global__ __launch_bounds__(256, 2) void gemm_h_kernel(
    const __half* __restrict__ A, const __half* __restrict__ Bt,
    const float* __restrict__ bias, const float* __restrict__ res,
    void* __restrict__ Cv, int M, int N, int K)
{
    extern __shared__ uint32_t smh[];
    const uint32_t smb = smem_u32(smh);
    const int tid = threadIdx.x;
    const int wid = tid >> 5, lane = tid & 31;
    const int g = lane >> 2, t = lane & 3;
    const int mi = lane >> 3, mr = lane & 7;
    const int rowoff = (mi & 1) * 8, koff = (mi >> 1) * 4;  // uint32 units
    const int warpM = (wid >> 2) * 64, warpN = (wid & 3) * 32;
    const int bm = blockIdx.y * 128, bn = blockIdx.x * 128;
    const int nch = K >> 6;

    const __half* Ab = A + (size_t)bm * K;
    const __half* Bb = Bt + (size_t)bn * K;

    // cp.async fill mapping: 1024 16B pieces/operand, 4 per thread
    const int frow = tid >> 1;                 // base rows: tid covers via idx
    (void)frow;

    // preload chunk 0 into stage 0
    {
#pragma unroll
        for (int r = 0; r < 4; r++) {
            const int idx = tid + 256 * r;
            const int row = idx >> 3, p = idx & 7;
            const uint32_t da = smb + (uint32_t)(row * 36 + p * 4) * 4;
            const uint32_t db = smb + (uint32_t)(2 * HSTG + row * 36 + p * 4) * 4;
            cp16(da, Ab + (size_t)row * K + p * 8);
            cp16(db, Bb + (size_t)row * K + p * 8);
        }
        CP_COMMIT();
    }

    float c[4][4][4];
#pragma unroll
    for (int i = 0; i < 4; i++)
#pragma unroll
        for (int j = 0; j < 4; j++)
#pragma unroll
            for (int q = 0; q < 4; q++) c[i][j][q] = 0.f;

    for (int ch = 0; ch < nch; ch++) {
        const int s = ch & 1;
        if (ch + 1 < nch) {
            const int k0 = (ch + 1) << 6;
#pragma unroll
            for (int r = 0; r < 4; r++) {
                const int idx = tid + 256 * r;
                const int row = idx >> 3, p = idx & 7;
                const uint32_t da = smb + (uint32_t)((s ^ 1) * HSTG + row * 36 + p * 4) * 4;
                const uint32_t db = smb + (uint32_t)((2 + (s ^ 1)) * HSTG + row * 36 + p * 4) * 4;
                cp16(da, Ab + (size_t)row * K + k0 + p * 8);
                cp16(db, Bb + (size_t)row * K + k0 + p * 8);
            }
            CP_COMMIT();
            CP_WAIT1();
        } else {
            CP_WAIT0();
        }
        __syncthreads();

        const uint32_t Ast = smb + (uint32_t)(s * HSTG) * 4;
        const uint32_t Bst = smb + (uint32_t)((2 + s) * HSTG) * 4;

        uint32_t bf[4][8];
#pragma unroll
        for (int j = 0; j < 4; j++) {
            const uint32_t ab = Bst + (uint32_t)((warpN + 8 * j + mr) * 36 + mi * 4) * 4;
            ldsm4(bf[j], ab);
            ldsm4(bf[j] + 4, ab + 64);
        }
#pragma unroll
        for (int i = 0; i < 4; i++) {
            uint32_t af[4][4];
            const uint32_t aa = Ast + (uint32_t)((warpM + 16 * i + rowoff + mr) * 36 + koff) * 4;
#pragma unroll
            for (int km = 0; km < 4; km++) ldsm4(af[km], aa + km * 32u);
#pragma unroll
            for (int j = 0; j < 4; j++) {
                mma_f16(c[i][j], af[0], bf[j][0], bf[j][1]);
                mma_f16(c[i][j], af[1], bf[j][2], bf[j][3]);
                mma_f16(c[i][j], af[2], bf[j][4], bf[j][5]);
                mma_f16(c[i][j], af[3], bf[j][6], bf[j][7]);
            }
        }
        __syncthreads();
    }

    // epilogue
#pragma unroll
    for (int i = 0; i < 4; i++) {
#pragma unroll
        for (int j = 0; j < 4; j++) {
            const int row0 = bm + warpM + 16 * i + g;
            const int col  = bn + warpN + 8 * j + 2 * t;
            const float b0 = bias[col], b1 = bias[col + 1];
            float v00 = c[i][j][0] + b0, v01 = c[i][j][1] + b1;
            float v10 = c[i][j][2] + b0, v11 = c[i][j][3] + b1;
            if (EPI == 1) {
                float* C = (float*)Cv;
                float2 r0 = *(const float2*)&res[(size_t)row0 * N + col];
                float2 r1 = *(const float2*)&res[(size_t)(row0 + 8) * N + col];
                *(float2*)&C[(size_t)row0 * N + col]       = make_float2(v00 + r0.x, v01 + r0.y);
                *(float2*)&C[(size_t)(row0 + 8) * N + col] = make_float2(v10 + r1.x, v11 + r1.y);
            } else if (EPI == 2) {
                __half* C = (__half*)Cv;
                *(__half2*)&C[(size_t)row0 * N + col] =
                    __floats2half2_rn(gelu_tanh(v00), gelu_tanh(v01));
                *(__half2*)&C[(size_t)(row0 + 8) * N + col] =
                    __floats2half2_rn(gelu_tanh(v10), gelu_tanh(v11));
            } else {  // EPI == 3
                __half* C = (__half*)Cv;
                *(__half2*)&C[(size_t)row0 * N + col]       = __floats2half2_rn(v00, v01);
                *(__half2*)&C[(size_t)(row0 + 8) * N + col] = __floats2half2_rn(v10, v11);
            }
        }
    }
}

// ---------------- tensor-core causal flash attention (fp16 mma, fp32 accum) ----
// reads fused qkv [MROWS][3072]; writes half att [MROWS][1024]
__global__ __launch_bounds__(256, 2) void attn_tc_kernel(
    const __half* __restrict__ QKV, __half* __restrict__ Oh)
{
    __shared__ uint32_t Qs[128][36];
    __shared__ uint32_t Ks[64][36];
    __shared__ uint32_t Vt[64][36];

    const int qt  = (int)gridDim.x - 1 - (int)blockIdx.x;
    const int bh  = blockIdx.y;
    const int b   = bh >> 4, h = bh & 15;
    const int tid = threadIdx.x, wid = tid >> 5, lane = tid & 31;
    const int g = lane >> 2, t = lane & 3;
    const int qb = qt * 128;
    const size_t bb = (size_t)b * T_SEQ;
    const int hq = h * HDIM, hk = hq + D_MODEL, hv = hq + 2 * D_MODEL;
    const int r0 = wid * 16;

#pragma unroll
    for (int r = 0; r < 4; r++) {
        const int lin = tid + 256 * r;
        const int row = lin >> 3, c = lin & 7;
        *(uint4*)&Qs[row][4 * c] =
            *(const uint4*)&QKV[(bb + qb + row) * QKV_N + hq + 8 * c];
    }
    __syncthreads();

    uint32_t qa[4][4];
    {
        const uint32_t qbase = smem_u32(Qs);
        const int mi = lane >> 3, mr = lane & 7;
        const int rowoff = (mi & 1) * 8, koff = (mi >> 1) * 4;
#pragma unroll
        for (int km = 0; km < 4; km++)
            ldsm4(qa[km], qbase + (uint32_t)((r0 + rowoff + mr) * 36 + km * 8 + koff) * 4);
    }

    float o[8][4];
#pragma unroll
    for (int j = 0; j < 8; j++)
#pragma unroll
        for (int q = 0; q < 4; q++) o[j][q] = 0.f;
    float m_g = -1e30f, m_g8 = -1e30f, l_g = 0.f, l_g8 = 0.f;
    const float SC = 0.18033688011112042f;  // (1/8) * log2(e)

    const uint32_t kbase = smem_u32(Ks), vbase = smem_u32(Vt);
    const int mi = lane >> 3, mr = lane & 7;

    const int nkt = 2 * qt + 2;
    for (int kt = 0; kt < nkt; kt++) {
        const int k0 = kt * 64;
#pragma unroll
        for (int r = 0; r < 2; r++) {
            const int lin = tid + 256 * r;
            const int row = lin >> 3, c = lin & 7;
            *(uint4*)&Ks[row][4 * c] =
                *(const uint4*)&QKV[(bb + k0 + row) * QKV_N + hk + 8 * c];
        }
        {
            const int kp = tid & 31, d8 = (tid >> 5) * 8;
            const __half* v0p = &QKV[(bb + k0 + 2 * kp) * QKV_N + hv + d8];
            uint4 v0 = *(const uint4*)v0p;
            uint4 v1 = *(const uint4*)(v0p + QKV_N);
            const ushort* a0 = (const ushort*)&v0;
            const ushort* a1 = (const ushort*)&v1;
#pragma unroll
            for (int i = 0; i < 8; i++)
                Vt[d8 + i][kp] = (uint32_t)a0[i] | ((uint32_t)a1[i] << 16);
        }
        __syncthreads();

        float s[8][4];
#pragma unroll
        for (int j = 0; j < 8; j++) {
            uint32_t kb[8];
            const uint32_t ab = kbase + (uint32_t)((8 * j + mr) * 36 + mi * 4) * 4;
            ldsm4(kb, ab);
            ldsm4(kb + 4, ab + 64);
            s[j][0] = s[j][1] = s[j][2] = s[j][3] = 0.f;
            mma_f16(s[j], qa[0], kb[0], kb[1]);
            mma_f16(s[j], qa[1], kb[2], kb[3]);
            mma_f16(s[j], qa[2], kb[4], kb[5]);
            mma_f16(s[j], qa[3], kb[6], kb[7]);
        }

        if (kt >= 2 * qt) {
            const int rg = qb + r0 + g;
#pragma unroll
            for (int j = 0; j < 8; j++) {
                const int col = k0 + 8 * j + 2 * t;
                if (col     > rg)     s[j][0] = -1e30f;
                if (col + 1 > rg)     s[j][1] = -1e30f;
                if (col     > rg + 8) s[j][2] = -1e30f;
                if (col + 1 > rg + 8) s[j][3] = -1e30f;
            }
        }

        float mg = -1e30f, mg8 = -1e30f;
#pragma unroll
        for (int j = 0; j < 8; j++) {
            mg  = fmaxf(mg,  fmaxf(s[j][0], s[j][1]));
            mg8 = fmaxf(mg8, fmaxf(s[j][2], s[j][3]));
        }
        mg  = fmaxf(mg,  __shfl_xor_sync(0xffffffffu, mg, 1));
        mg  = fmaxf(mg,  __shfl_xor_sync(0xffffffffu, mg, 2));
        mg8 = fmaxf(mg8, __shfl_xor_sync(0xffffffffu, mg8, 1));
        mg8 = fmaxf(mg8, __shfl_xor_sync(0xffffffffu, mg8, 2));
        const float mng  = fmaxf(m_g, mg);
        const float mng8 = fmaxf(m_g8, mg8);
        const float corr  = fast_ex2((m_g  - mng)  * SC);
        const float corr8 = fast_ex2((m_g8 - mng8) * SC);
        float sg = 0.f, sg8 = 0.f;
#pragma unroll
        for (int j = 0; j < 8; j++) {
            s[j][0] = fast_ex2((s[j][0] - mng)  * SC);
            s[j][1] = fast_ex2((s[j][1] - mng)  * SC);
            s[j][2] = fast_ex2((s[j][2] - mng8) * SC);
            s[j][3] = fast_ex2((s[j][3] - mng8) * SC);
            sg  += s[j][0] + s[j][1];
            sg8 += s[j][2] + s[j][3];
        }
        sg  += __shfl_xor_sync(0xffffffffu, sg, 1);
        sg  += __shfl_xor_sync(0xffffffffu, sg, 2);
        sg8 += __shfl_xor_sync(0xffffffffu, sg8, 1);
        sg8 += __shfl_xor_sync(0xffffffffu, sg8, 2);
        l_g  = l_g  * corr  + sg;
        l_g8 = l_g8 * corr8 + sg8;
        m_g = mng; m_g8 = mng8;
#pragma unroll
        for (int j = 0; j < 8; j++) {
            o[j][0] *= corr;  o[j][1] *= corr;
            o[j][2] *= corr8; o[j][3] *= corr8;
        }

        uint32_t pa[4][4];
#pragma unroll
        for (int km = 0; km < 4; km++) {
            pa[km][0] = f22h2(s[2 * km][0], s[2 * km][1]);
            pa[km][1] = f22h2(s[2 * km][2], s[2 * km][3]);
            pa[km][2] = f22h2(s[2 * km + 1][0], s[2 * km + 1][1]);
            pa[km][3] = f22h2(s[2 * km + 1][2], s[2 * km + 1][3]);
        }

#pragma unroll
        for (int j = 0; j < 8; j++) {
            uint32_t vb[8];
            const uint32_t ab = vbase + (uint32_t)((8 * j + mr) * 36 + mi * 4) * 4;
            ldsm4(vb, ab);
            ldsm4(vb + 4, ab + 64);
            mma_f16(o[j], pa[0], vb[0], vb[1]);
            mma_f16(o[j], pa[1], vb[2], vb[3]);
            mma_f16(o[j], pa[2], vb[4], vb[5]);
            mma_f16(o[j], pa[3], vb[6], vb[7]);
        }
        __syncthreads();
    }

    const float ig = 1.0f / l_g, ig8 = 1.0f / l_g8;
    __half* Og = Oh + (bb + qb + r0) * D_MODEL + hq;
#pragma unroll
    for (int j = 0; j < 8; j++) {
        const int col = 8 * j + 2 * t;
        *(__half2*)&Og[(size_t)g * D_MODEL + col] =
            __floats2half2_rn(o[j][0] * ig, o[j][1] * ig);
        *(__half2*)&Og[(size_t)(g + 8) * D_MODEL + col] =
            __floats2half2_rn(o[j][2] * ig8, o[j][3] * ig8);
    }
}

// ---------------- launch ----------------
extern "C" void kernel_launch(void* const* d_in, const int* in_sizes, int n_in,
                              void* d_out, int out_size)
{
    const float* x    = (const float*)d_in[0];
    const float* ln1s = (const float*)d_in[2];
    const float* ln1b = (const float*)d_in[3];
    const float* wq = (const float*)d_in[4];  const float* bq = (const float*)d_in[5];
    const float* wk = (const float*)d_in[6];  const float* bk = (const float*)d_in[7];
    const float* wv = (const float*)d_in[8];  const float* bv = (const float*)d_in[9];
    const float* wo = (const float*)d_in[10]; const float* bo = (const float*)d_in[11];
    const float* ln2s = (const float*)d_in[12];
    const float* ln2b = (const float*)d_in[13];
    const float* w1 = (const float*)d_in[14]; const float* b1 = (const float*)d_in[15];
    const float* w2 = (const float*)d_in[16]; const float* b2 = (const float*)d_in[17];
    float* out = (float*)d_out;

    __half *h1, *qkv, *att, *ff, *wqkvT, *woT, *w1T, *w2T;
    float *res, *bqkv;
    cudaGetSymbolAddress((void**)&h1,   g_h1);
    cudaGetSymbolAddress((void**)&qkv,  g_qkv);
    cudaGetSymbolAddress((void**)&att,  g_att);
    cudaGetSymbolAddress((void**)&res,  g_res);
    cudaGetSymbolAddress((void**)&ff,   g_ff);
    cudaGetSymbolAddress((void**)&wqkvT, g_wqkvT);
    cudaGetSymbolAddress((void**)&woT,  g_woT);
    cudaGetSymbolAddress((void**)&w1T,  g_w1T);
    cudaGetSymbolAddress((void**)&w2T,  g_w2T);
    cudaGetSymbolAddress((void**)&bqkv, g_bqkv);

    cudaFuncSetAttribute(gemm_h_kernel<1>, cudaFuncAttributeMaxDynamicSharedMemorySize, GEMM_SMEM);
    cudaFuncSetAttribute(gemm_h_kernel<2>, cudaFuncAttributeMaxDynamicSharedMemorySize, GEMM_SMEM);
    cudaFuncSetAttribute(gemm_h_kernel<3>, cudaFuncAttributeMaxDynamicSharedMemorySize, GEMM_SMEM);

    const dim3 tb(32, 8);
    transpose_h_kernel<<<dim3(D_MODEL / 32, D_MODEL / 32), tb>>>(wq, wqkvT, D_MODEL, D_MODEL);
    transpose_h_kernel<<<dim3(D_MODEL / 32, D_MODEL / 32), tb>>>(wk, wqkvT + (size_t)D_MODEL * D_MODEL, D_MODEL, D_MODEL);
    transpose_h_kernel<<<dim3(D_MODEL / 32, D_MODEL / 32), tb>>>(wv, wqkvT + (size_t)2 * D_MODEL * D_MODEL, D_MODEL, D_MODEL);
    transpose_h_kernel<<<dim3(D_MODEL / 32, D_MODEL / 32), tb>>>(wo, woT, D_MODEL, D_MODEL);
    transpose_h_kernel<<<dim3(DFF / 32, D_MODEL / 32), tb>>>(w1, w1T, D_MODEL, DFF);
    transpose_h_kernel<<<dim3(D_MODEL / 32, DFF / 32), tb>>>(w2, w2T, DFF, D_MODEL);
    bias_concat_kernel<<<QKV_N / 256, 256>>>(bq, bk, bv, bqkv);

    const dim3 gQKV(QKV_N / 128, MROWS / 128);   // (24, 64)
    const dim3 gD(D_MODEL / 128, MROWS / 128);   // (8, 64)
    const dim3 gF(DFF / 128,     MROWS / 128);   // (32, 64)

    ln_kernel<<<MROWS, 256>>>(x, ln1s, ln1b, h1);
    gemm_h_kernel<3><<<gQKV, 256, GEMM_SMEM>>>(h1, wqkvT, bqkv, nullptr, qkv, MROWS, QKV_N, D_MODEL);
    attn_tc_kernel<<<dim3(T_SEQ / 128, BATCH * NHEAD), 256>>>(qkv, att);
    gemm_h_kernel<1><<<gD, 256, GEMM_SMEM>>>(att, woT, bo, x, res, MROWS, D_MODEL, D_MODEL);
    ln_kernel<<<MROWS, 256>>>(res, ln2s, ln2b, h1);
    gemm_h_kernel<2><<<gF, 256, GEMM_SMEM>>>(h1, w1T, b1, nullptr, ff, MROWS, DFF, D_MODEL);
    gemm_h_kernel<1><<<gD, 256, GEMM_SMEM>>>(ff, w2T, b2, res, out, MROWS, D_MODEL, DFF);
}